// round 16
// baseline (speedup 1.0000x reference)
#include <cuda_runtime.h>
#include <cstdint>

#define B_  16
#define T_  128
#define C_  256
#define HW_ 1024

// ---------------- scratch (static device globals; no cudaMalloc allowed) ----
__device__ float g_WkT  [HW_ * C_];         // W_sK^T [HW, C]
__device__ float g_FsT  [B_ * C_ * HW_];    // F_s^T per batch [C, HW]
__device__ float g_Wp   [16 * C_ * C_];     // Wcomb split-K partials
__device__ float g_Wc   [C_ * C_];          // Wcomb = W_aQ @ WkT
__device__ float g_bc   [C_];               // bcomb = b_aQ @ WkT
__device__ float g_bsV  [C_];               // b_sV / T
__device__ float g_Qw   [B_ * T_  * C_];    // Qw = F_a @ Wcomb + bcomb
__device__ float g_QK   [B_ * T_  * HW_];   // QK -> Kmat -> (sinkhorn) Kmat⊙v
__device__ float g_Gp   [4 * B_ * T_ * C_]; // G split-K partials
__device__ float g_G    [B_ * T_  * C_];    // u ⊙ (Kmat⊙v) @ F_s
__device__ float g_O    [B_ * T_  * C_];    // G @ W_sV + b_sV/T
__device__ float g_H    [B_ * T_  * 3*C_];  // relu(O@W1+b1)
__device__ float g_yp   [3 * B_ * T_ * C_]; // y split-K partials
__device__ float g_u    [B_ * T_];
__device__ float g_v    [B_ * HW_];
__device__ int   g_iter_fallback = 100;

// ---------------- SIMT SGEMM, NN only; double-buffered k-pipeline -----------
// (round-15 benched form, verbatim)
template <int BM>
__global__ __launch_bounds__(256) void sgemm(
    const float* __restrict__ A, const float* __restrict__ Bm,
    const float* __restrict__ bias, const float* __restrict__ rscale,
    float* __restrict__ C,
    int M, int N, int K, int lda,
    long long sA, long long sB, long long sC,
    int rsStride, int doRelu, int kChunks)
{
    constexpr int TM = BM / 16;
    constexpr int AR = BM / 64;
    __shared__ float As[2][16][BM];    // [buf][k][m]
    __shared__ float Bs[2][16][68];    // [buf][k][n]

    const int bz  = blockIdx.z;
    const int bz2 = bz / kChunks;
    const int kc  = bz - bz2 * kChunks;
    const float* Ab = A  + (long long)bz2 * sA + (long long)kc * K;
    const float* Bb = Bm + (long long)bz2 * sB + (long long)kc * K * N;
    float*       Cb = C  + (long long)bz * sC;

    const int m0 = blockIdx.y * BM;
    const int n0 = blockIdx.x * 64;
    const int tid = threadIdx.x;
    const int tx = tid & 15;
    const int ty = tid >> 4;

    const int a_k4 = (tid & 3) << 2;
    const int a_m  = tid >> 2;
    const int b_n4 = (tid & 15) << 2;
    const int b_k  = tid >> 4;

    float acc[TM][4];
#pragma unroll
    for (int i = 0; i < TM; ++i)
#pragma unroll
        for (int j = 0; j < 4; ++j) acc[i][j] = 0.f;

    const int NIT = K >> 4;
    float4 ra[AR], rb;

#pragma unroll
    for (int r = 0; r < AR; ++r)
        ra[r] = *(const float4*)(Ab + (long long)(m0 + a_m + (r << 6)) * lda + a_k4);
    rb = *(const float4*)(Bb + (long long)b_k * N + (n0 + b_n4));
#pragma unroll
    for (int r = 0; r < AR; ++r) {
        int m = a_m + (r << 6);
        As[0][a_k4 + 0][m] = ra[r].x; As[0][a_k4 + 1][m] = ra[r].y;
        As[0][a_k4 + 2][m] = ra[r].z; As[0][a_k4 + 3][m] = ra[r].w;
    }
    *(float4*)(&Bs[0][b_k][b_n4]) = rb;
    if (NIT > 1) {
#pragma unroll
        for (int r = 0; r < AR; ++r)
            ra[r] = *(const float4*)(Ab + (long long)(m0 + a_m + (r << 6)) * lda + (16 + a_k4));
        rb = *(const float4*)(Bb + (long long)(16 + b_k) * N + (n0 + b_n4));
    }
    __syncthreads();

    for (int it = 0; it < NIT; ++it) {
        const int cur = it & 1;
        if (it + 1 < NIT) {
            const int nxt = cur ^ 1;
#pragma unroll
            for (int r = 0; r < AR; ++r) {
                int m = a_m + (r << 6);
                As[nxt][a_k4 + 0][m] = ra[r].x; As[nxt][a_k4 + 1][m] = ra[r].y;
                As[nxt][a_k4 + 2][m] = ra[r].z; As[nxt][a_k4 + 3][m] = ra[r].w;
            }
            *(float4*)(&Bs[nxt][b_k][b_n4]) = rb;
            if (it + 2 < NIT) {
                const int k0 = (it + 2) << 4;
#pragma unroll
                for (int r = 0; r < AR; ++r)
                    ra[r] = *(const float4*)(Ab + (long long)(m0 + a_m + (r << 6)) * lda + (k0 + a_k4));
                rb = *(const float4*)(Bb + (long long)(k0 + b_k) * N + (n0 + b_n4));
            }
        }
#pragma unroll
        for (int k = 0; k < 16; ++k) {
            float af[TM], bf[4];
#pragma unroll
            for (int i = 0; i < TM; i += 4)
                *(float4*)&af[i] = *(const float4*)&As[cur][k][ty * TM + i];
            *(float4*)&bf[0] = *(const float4*)&Bs[cur][k][tx << 2];
#pragma unroll
            for (int i = 0; i < TM; ++i)
#pragma unroll
                for (int j = 0; j < 4; ++j)
                    acc[i][j] = fmaf(af[i], bf[j], acc[i][j]);
        }
        __syncthreads();
    }

#pragma unroll
    for (int i = 0; i < TM; ++i) {
        int m = m0 + ty * TM + i;
        float rs = rscale ? rscale[(long long)bz2 * rsStride + m] : 1.f;
        float vals[4];
#pragma unroll
        for (int j = 0; j < 4; ++j) {
            float x = acc[i][j];
            if (bias) x += bias[n0 + (tx << 2) + j];
            x *= rs;
            if (doRelu) x = fmaxf(x, 0.f);
            vals[j] = x;
        }
        *(float4*)(Cb + (long long)m * N + n0 + (tx << 2)) = *(float4*)vals;
    }
}

// ---------------- Wcomb split-K reduce ---------------------------------------
__global__ __launch_bounds__(256) void wcomb_reduce(
    const float* __restrict__ Wp, float* __restrict__ Wc)
{
    int i = blockIdx.x * 256 + threadIdx.x;
    float s = 0.f;
#pragma unroll
    for (int z = 0; z < 16; ++z) s += Wp[z * (C_ * C_) + i];
    Wc[i] = s;
}

// ---------------- G split-K reduce: G = u ⊙ sum_z Gp[b*4+z] -----------------
__global__ __launch_bounds__(256) void greduce(
    const float* __restrict__ Gp, const float* __restrict__ u,
    float* __restrict__ G)
{
    int i = blockIdx.x * 256 + threadIdx.x;
    int b   = i >> 15;
    int rem = i & 32767;
    float s = 0.f;
#pragma unroll
    for (int z = 0; z < 4; ++z)
        s += Gp[(long long)((b << 2) + z) * (T_ * C_) + rem];
    G[i] = u[i >> 8] * s;
}

// ---------------- y split-K reduce: y = sum_z yp[z] + b2 --------------------
__global__ __launch_bounds__(256) void yreduce(
    const float* __restrict__ yp, const float* __restrict__ b2,
    float* __restrict__ y)
{
    int i = blockIdx.x * 256 + threadIdx.x;
    float s = 0.f;
#pragma unroll
    for (int z = 0; z < 3; ++z)
        s += yp[(long long)z * (B_ * T_ * C_) + i];
    y[i] = s + b2[i & (C_ - 1)];
}

// ---------------- tiled transpose -------------------------------------------
__global__ __launch_bounds__(256) void transpose_k(
    const float* __restrict__ in, float* __restrict__ out,
    int R, int Cc, long long sIn, long long sOut)
{
    __shared__ float t[32][33];
    const float* ib = in  + (long long)blockIdx.z * sIn;
    float*       ob = out + (long long)blockIdx.z * sOut;
    const int r0 = blockIdx.y << 5;
    const int c0 = blockIdx.x << 5;
    const int lx = threadIdx.x & 31;
    const int ly = threadIdx.x >> 5;
#pragma unroll
    for (int i = ly; i < 32; i += 8)
        t[i][lx] = ib[(long long)(r0 + i) * Cc + (c0 + lx)];
    __syncthreads();
#pragma unroll
    for (int i = ly; i < 32; i += 8)
        ob[(long long)(c0 + i) * R + (r0 + lx)] = t[lx][i];
}

// ---------------- bias prep --------------------------------------------------
__global__ __launch_bounds__(256) void prep_bias(
    const float* __restrict__ W_sK, const float* __restrict__ b_aQ,
    const float* __restrict__ b_sV,
    float* __restrict__ bc, float* __restrict__ bsV)
{
    __shared__ float red[256];
    const int c = blockIdx.x;
    const int tid = threadIdx.x;
    if (c == 0) bsV[tid] = b_sV[tid] * (1.f / (float)T_);
    const float* row = W_sK + (long long)c * HW_;
    float s = 0.f;
#pragma unroll
    for (int r = 0; r < 4; ++r) {
        int h = tid + (r << 8);
        s = fmaf(row[h], b_aQ[h], s);
    }
    red[tid] = s; __syncthreads();
    for (int st = 128; st; st >>= 1) { if (tid < st) red[tid] += red[tid + st]; __syncthreads(); }
    if (tid == 0) bc[c] = red[0];
}

// ---------------- masked softmax -> Kmat = exp(10*S - 10), in place ---------
__global__ __launch_bounds__(256) void softmax_kmat(
    float* __restrict__ ZK, const int* __restrict__ Ms)
{
    __shared__ float red[256];
    const int row = blockIdx.x;        // b*T + t
    const int b   = row >> 7;
    float* z = ZK + (long long)row * HW_;
    const int* mrow = Ms + b * HW_;
    const int tid = threadIdx.x;

    float zv[4]; int mv[4];
    float mx = -3.4e38f;
#pragma unroll
    for (int c = 0; c < 4; ++c) {
        int h = tid + (c << 8);
        zv[c] = z[h];
        mv[c] = mrow[h];
        if (mv[c]) mx = fmaxf(mx, zv[c]);
    }
    red[tid] = mx; __syncthreads();
    for (int s = 128; s; s >>= 1) { if (tid < s) red[tid] = fmaxf(red[tid], red[tid + s]); __syncthreads(); }
    mx = red[0]; __syncthreads();

    float ev[4], sum = 0.f;
#pragma unroll
    for (int c = 0; c < 4; ++c) {
        ev[c] = mv[c] ? expf(zv[c] - mx) : 0.f;
        sum += ev[c];
    }
    red[tid] = sum; __syncthreads();
    for (int s = 128; s; s >>= 1) { if (tid < s) red[tid] += red[tid + s]; __syncthreads(); }
    const float inv = 1.f / red[0];

#pragma unroll
    for (int c = 0; c < 4; ++c) {
        int h = tid + (c << 8);
        float S = ev[c] * inv;
        z[h] = expf(10.f * S - 10.f);     // exp(-(1-S)/0.1)
    }
}

// ---------------- cluster helpers --------------------------------------------
__device__ __forceinline__ uint32_t smem_u32(const void* p) {
    uint32_t a;
    asm("{ .reg .u64 t; cvta.to.shared.u64 t, %1; cvt.u32.u64 %0, t; }"
        : "=r"(a) : "l"(p));
    return a;
}
__device__ __forceinline__ void cluster_sync_() {
    asm volatile("barrier.cluster.arrive.aligned;" ::: "memory");
    asm volatile("barrier.cluster.wait.aligned;"  ::: "memory");
}
__device__ __forceinline__ float ld_peer_f32(uint32_t addr, uint32_t rank) {
    uint32_t r; float v;
    asm volatile("mapa.shared::cluster.u32 %0, %1, %2;" : "=r"(r) : "r"(addr), "r"(rank));
    asm volatile("ld.shared::cluster.f32 %0, [%1];"     : "=f"(v) : "r"(r));
    return v;
}
// release-arrive on peer-rank mbarrier (validated protocol from R11, count now 8)
__device__ __forceinline__ void arrive_peer_release(uint32_t mbar, uint32_t rank) {
    uint32_t r;
    asm volatile("mapa.shared::cluster.u32 %0, %1, %2;" : "=r"(r) : "r"(mbar), "r"(rank));
    asm volatile("mbarrier.arrive.release.cluster.shared::cluster.b64 _, [%0];"
                 :: "r"(r) : "memory");
}
// acquire-wait (cluster scope) on local mbarrier phase parity
__device__ __forceinline__ void mbar_wait_parity_cluster(uint32_t mbar, uint32_t parity) {
    asm volatile(
        "{\n\t"
        ".reg .pred P;\n\t"
        "WAIT_%=:\n\t"
        "mbarrier.try_wait.parity.acquire.cluster.shared::cta.b64 P, [%0], %1, 0x989680;\n\t"
        "@P bra DONE_%=;\n\t"
        "bra WAIT_%=;\n\t"
        "DONE_%=:\n\t"
        "}"
        :: "r"(mbar), "r"(parity) : "memory");
}

// ---------------- Sinkhorn: benched pull data path; mbarrier exchange -------
// Identical compute + peer-LOAD data path to the round-9/14/15 benched form.
// ONLY the per-iteration cluster_sync is replaced: lanes 0-7 fire one
// release-arrive each to rank=lane's barrier (8 parallel remote arrives,
// count=8), waiters do an acquire try_wait on the local barrier (parity=it&1).
// Any CTA's iter-(i+1) arrive implies all CTAs issued their iter-i arrives,
// hence committed their iter-i pbuf writes; slots parity-double-buffered;
// pbuf[p] reuse at iter i+2 is gated by the phase-(i+1) wait.
__global__ void __cluster_dims__(8, 1, 1) __launch_bounds__(256, 1)
sinkhorn(float* __restrict__ Km, const int* __restrict__ Ms,
         const int* __restrict__ nIterPtr,
         float* __restrict__ gu, float* __restrict__ gv)
{
    extern __shared__ float sm[];
    float* Kt    = sm;                   // 128 * 129
    float* u     = Kt + 128 * 129;       // 128
    float* v     = u  + 128;             // 128
    float* bv    = v  + 128;             // 128
    float* red   = bv + 128;             // 256
    float* pbuf  = red + 256;            // 2 * 128
    float* mbarf = pbuf + 256;           // 8 bytes (offset 69632, 8-aligned)

    const int rank = blockIdx.x;
    const int b    = blockIdx.y;
    const int h0   = rank << 7;
    const int tid  = threadIdx.x;

    const uint32_t mbar_a = smem_u32(mbarf);
    if (tid == 0) {
        asm volatile("mbarrier.init.shared.b64 [%0], %1;"
                     :: "r"(mbar_a), "r"(8u) : "memory");
    }

    const int* mrow = Ms + b * HW_;
    float msum = 0.f;
    for (int h = tid; h < HW_; h += 256) msum += (float)mrow[h];
    red[tid] = msum; __syncthreads();
    for (int s = 128; s; s >>= 1) { if (tid < s) red[tid] += red[tid + s]; __syncthreads(); }
    const float num_fg = red[0];
    __syncthreads();
    if (tid < 128) {
        bv[tid] = mrow[h0 + tid] ? 1.f / num_fg : 0.f;
        u[tid]  = 1.f / (float)T_;
    }

    float* Kb = Km + (long long)b * T_ * HW_ + h0;
    for (int idx = tid; idx < 128 * 128; idx += 256) {
        int t = idx >> 7, hl = idx & 127;
        Kt[t * 129 + hl] = Kb[(long long)t * HW_ + hl];
    }
    __syncthreads();
    cluster_sync_();   // all 8 barriers initialized before any remote arrive

    const int niter = *nIterPtr;
    const int col  = tid & 127;
    const int half = tid >> 7;
    const uint32_t pbuf_addr = smem_u32(pbuf);

    for (int it = 0; it < niter; ++it) {
        const int p = it & 1;

        // phase 1: Ktu_h = sum_t K[t,h]*u[t]  (benched scalar walk)
        float s1 = 0.f;
        {
            const float* kp = Kt + (half << 6) * 129 + col;
            const float* up = u + (half << 6);
#pragma unroll 8
            for (int t = 0; t < 64; ++t) s1 = fmaf(kp[t * 129], up[t], s1);
        }
        red[tid] = s1; __syncthreads();
        if (tid < 128) {
            float ktu = red[tid] + red[tid + 128];
            float bb = bv[tid];
            v[tid] = (bb > 0.f) ? bb / ktu : 0.f;
        }
        __syncthreads();

        // phase 2: partial Kv_t over local columns (benched scalar walk)
        float s2 = 0.f;
        {
            const float* kp = Kt + col * 129 + (half << 6);
            const float* vp = v + (half << 6);
#pragma unroll 8
            for (int hh = 0; hh < 64; ++hh) s2 = fmaf(kp[hh], vp[hh], s2);
        }
        red[tid] = s2; __syncthreads();
        if (tid < 128) pbuf[(p << 7) + tid] = red[tid] + red[tid + 128];
        __syncthreads();   // pbuf writes committed before arrives

        // exchange: 8 parallel remote release-arrives, then local acquire-wait
        if (tid < 8) arrive_peer_release(mbar_a, (uint32_t)tid);
        mbar_wait_parity_cluster(mbar_a, (uint32_t)p);

        if (tid < 128) {
            float kv = 0.f;
#pragma unroll
            for (int r = 0; r < 8; ++r)
                kv += ld_peer_f32(pbuf_addr + (((p << 7) + tid) << 2), (uint32_t)r);
            u[tid] = (1.f / (float)T_) / kv;
        }
        __syncthreads();
    }

    if (tid < 128) {
        if (rank == 0) gu[b * T_ + tid] = u[tid];
        gv[b * HW_ + h0 + tid] = v[tid];
    }

    // epilogue: write Kmat ⊙ v back in place (u applied in greduce)
    for (int idx = tid; idx < 128 * 128; idx += 256) {
        int t = idx >> 7, hl = idx & 127;
        Kb[(long long)t * HW_ + hl] = Kt[t * 129 + hl] * v[hl];
    }

    cluster_sync_();   // keep SMEM alive until all peers finished reading
}

// ---------------- driver ------------------------------------------------------
extern "C" void kernel_launch(void* const* d_in, const int* in_sizes, int n_in,
                              void* d_out, int out_size)
{
    const float* F_a  = (const float*)d_in[0];
    const float* F_s  = (const float*)d_in[1];
    const int*   M_s  = (const int*)  d_in[2];
    const float* W_aQ = (const float*)d_in[3];
    const float* b_aQ = (const float*)d_in[4];
    const float* W_sK = (const float*)d_in[5];
    // d_in[6] = b_sK : per-(b,t)-row logit constant, cancels in softmax over k
    const float* W_sV = (const float*)d_in[7];
    const float* b_sV = (const float*)d_in[8];
    const float* W1   = (const float*)d_in[9];
    const float* b1   = (const float*)d_in[10];
    const float* W2   = (const float*)d_in[11];
    const float* b2   = (const float*)d_in[12];
    float* y = (float*)d_out;

    float *WkT, *FsT, *Wp, *Wc, *bc, *bsV, *Qw, *QK, *Gp, *G, *O, *H, *yp, *u, *v;
    int* itf;
    cudaGetSymbolAddress((void**)&WkT, g_WkT);
    cudaGetSymbolAddress((void**)&FsT, g_FsT);
    cudaGetSymbolAddress((void**)&Wp,  g_Wp);
    cudaGetSymbolAddress((void**)&Wc,  g_Wc);
    cudaGetSymbolAddress((void**)&bc,  g_bc);
    cudaGetSymbolAddress((void**)&bsV, g_bsV);
    cudaGetSymbolAddress((void**)&Qw,  g_Qw);
    cudaGetSymbolAddress((void**)&QK,  g_QK);
    cudaGetSymbolAddress((void**)&Gp,  g_Gp);
    cudaGetSymbolAddress((void**)&G,   g_G);
    cudaGetSymbolAddress((void**)&O,   g_O);
    cudaGetSymbolAddress((void**)&H,   g_H);
    cudaGetSymbolAddress((void**)&yp,  g_yp);
    cudaGetSymbolAddress((void**)&u,   g_u);
    cudaGetSymbolAddress((void**)&v,   g_v);
    cudaGetSymbolAddress((void**)&itf, g_iter_fallback);

    const int* iterp = (n_in > 13 && d_in[13]) ? (const int*)d_in[13]
                                               : (const int*)itf;

    const int SK_SMEM = (128 * 129 + 128 * 3 + 256 + 256 + 4) * 4;  // 69648 B
    cudaFuncSetAttribute(sinkhorn, cudaFuncAttributeMaxDynamicSharedMemorySize, SK_SMEM);

    // 0a) WkT = W_sK^T                 [256,1024] -> [1024,256]
    transpose_k<<<dim3(HW_ / 32, C_ / 32, 1), 256>>>(W_sK, WkT, C_, HW_, 0, 0);
    // 0b) FsT[b] = F_s[b]^T            [1024,256] -> [256,1024], batched
    transpose_k<<<dim3(C_ / 32, HW_ / 32, B_), 256>>>(
        F_s, FsT, HW_, C_, (long long)HW_ * C_, (long long)C_ * HW_);
    // 0c) bcomb + b_sV/T
    prep_bias<<<C_, 256>>>(W_sK, b_aQ, b_sV, bc, bsV);

    // 1) Wcomb split-K (16 chunks of 64, grid 256) + reduce
    sgemm<64><<<dim3(4, 4, 16), 256>>>(
        W_aQ, WkT, nullptr, nullptr, Wp,
        C_, C_, 64, HW_, 0, 0, (long long)C_ * C_, 0, 0, 16);
    wcomb_reduce<<<(C_ * C_) / 256, 256>>>(Wp, Wc);

    // 2) Qw = F_a @ Wcomb + bcomb      [2048,256] k=256 (NN, BM=64)
    sgemm<64><<<dim3(4, 32, 1), 256>>>(
        F_a, Wc, bc, nullptr, Qw, B_ * T_, C_, C_, C_, 0, 0, 0, 0, 0, 1);

    // 3) QK[b] = Qw[b] @ FsT[b]        batched [128,1024] k=256 (NN, BM=64)
    sgemm<64><<<dim3(16, 2, B_), 256>>>(
        Qw, FsT, nullptr, nullptr, QK, T_, HW_, C_, C_,
        (long long)T_ * C_, (long long)C_ * HW_, (long long)T_ * HW_, 0, 0, 1);

    // 4) masked softmax -> Kmat (in place)
    softmax_kmat<<<B_ * T_, 256>>>(QK, M_s);

    // 5) Sinkhorn -> u, v; epilogue writes Kmat⊙v in place
    sinkhorn<<<dim3(8, B_), 256, SK_SMEM>>>(QK, M_s, iterp, u, v);

    // 6) Gp split-K (z = b*4+c, grid 512); u applied in greduce
    sgemm<64><<<dim3(4, 2, B_ * 4), 256>>>(
        QK, F_s, nullptr, nullptr, Gp, T_, C_, 256, HW_,
        (long long)T_ * HW_, (long long)HW_ * C_, (long long)T_ * C_, 0, 0, 4);
    greduce<<<(B_ * T_ * C_) / 256, 256>>>(Gp, u, G);

    // 7) O = G @ W_sV + b_sV/T         [2048,256] k=256 (NN, BM=64)
    sgemm<64><<<dim3(4, 32, 1), 256>>>(
        G, W_sV, bsV, nullptr, O, B_ * T_, C_, C_, C_, 0, 0, 0, 0, 0, 1);

    // 8) H = relu(O @ W1 + b1)         [2048,768] k=256 (NN, BM=64)
    sgemm<64><<<dim3(12, 32, 1), 256>>>(
        O, W1, b1, nullptr, H, B_ * T_, 3 * C_, C_, C_, 0, 0, 0, 0, 1, 1);

    // 9) yp split-K 3 (grid 384) + reduce(+b2)
    sgemm<64><<<dim3(4, 32, 3), 256>>>(
        H, W2, nullptr, nullptr, yp, B_ * T_, C_, 256, 3 * C_,
        0, 0, (long long)B_ * T_ * C_, 0, 0, 3);
    yreduce<<<(B_ * T_ * C_) / 256, 256>>>(yp, b2, y);
}

// round 17
// speedup vs baseline: 1.1572x; 1.1572x over previous
#include <cuda_runtime.h>
#include <cstdint>

#define B_  16
#define T_  128
#define C_  256
#define HW_ 1024

// ---------------- scratch (static device globals; no cudaMalloc allowed) ----
__device__ float g_WkT  [HW_ * C_];         // W_sK^T [HW, C]
__device__ float g_FsT  [B_ * C_ * HW_];    // F_s^T per batch [C, HW]
__device__ float g_Wp   [16 * C_ * C_];     // Wcomb split-K partials
__device__ float g_Wc   [C_ * C_];          // Wcomb = W_aQ @ WkT
__device__ float g_bc   [C_];               // bcomb = b_aQ @ WkT
__device__ float g_bsV  [C_];               // b_sV / T
__device__ float g_Qw   [B_ * T_  * C_];    // Qw = F_a @ Wcomb + bcomb
__device__ float g_QK   [B_ * T_  * HW_];   // QK -> Kmat -> (sinkhorn) Kmat⊙v
__device__ float g_Gp   [4 * B_ * T_ * C_]; // G split-K partials
__device__ float g_G    [B_ * T_  * C_];    // u ⊙ (Kmat⊙v) @ F_s
__device__ float g_O    [B_ * T_  * C_];    // G @ W_sV + b_sV/T
__device__ float g_H    [B_ * T_  * 3*C_];  // relu(O@W1+b1)
__device__ float g_yp   [3 * B_ * T_ * C_]; // y split-K partials
__device__ float g_u    [B_ * T_];
__device__ float g_v    [B_ * HW_];
__device__ int   g_iter_fallback = 100;

// ---------------- SIMT SGEMM, NN only; double-buffered k-pipeline -----------
// (round-15 benched form, verbatim)
template <int BM>
__global__ __launch_bounds__(256) void sgemm(
    const float* __restrict__ A, const float* __restrict__ Bm,
    const float* __restrict__ bias, const float* __restrict__ rscale,
    float* __restrict__ C,
    int M, int N, int K, int lda,
    long long sA, long long sB, long long sC,
    int rsStride, int doRelu, int kChunks)
{
    constexpr int TM = BM / 16;
    constexpr int AR = BM / 64;
    __shared__ float As[2][16][BM];    // [buf][k][m]
    __shared__ float Bs[2][16][68];    // [buf][k][n]

    const int bz  = blockIdx.z;
    const int bz2 = bz / kChunks;
    const int kc  = bz - bz2 * kChunks;
    const float* Ab = A  + (long long)bz2 * sA + (long long)kc * K;
    const float* Bb = Bm + (long long)bz2 * sB + (long long)kc * K * N;
    float*       Cb = C  + (long long)bz * sC;

    const int m0 = blockIdx.y * BM;
    const int n0 = blockIdx.x * 64;
    const int tid = threadIdx.x;
    const int tx = tid & 15;
    const int ty = tid >> 4;

    const int a_k4 = (tid & 3) << 2;
    const int a_m  = tid >> 2;
    const int b_n4 = (tid & 15) << 2;
    const int b_k  = tid >> 4;

    float acc[TM][4];
#pragma unroll
    for (int i = 0; i < TM; ++i)
#pragma unroll
        for (int j = 0; j < 4; ++j) acc[i][j] = 0.f;

    const int NIT = K >> 4;
    float4 ra[AR], rb;

#pragma unroll
    for (int r = 0; r < AR; ++r)
        ra[r] = *(const float4*)(Ab + (long long)(m0 + a_m + (r << 6)) * lda + a_k4);
    rb = *(const float4*)(Bb + (long long)b_k * N + (n0 + b_n4));
#pragma unroll
    for (int r = 0; r < AR; ++r) {
        int m = a_m + (r << 6);
        As[0][a_k4 + 0][m] = ra[r].x; As[0][a_k4 + 1][m] = ra[r].y;
        As[0][a_k4 + 2][m] = ra[r].z; As[0][a_k4 + 3][m] = ra[r].w;
    }
    *(float4*)(&Bs[0][b_k][b_n4]) = rb;
    if (NIT > 1) {
#pragma unroll
        for (int r = 0; r < AR; ++r)
            ra[r] = *(const float4*)(Ab + (long long)(m0 + a_m + (r << 6)) * lda + (16 + a_k4));
        rb = *(const float4*)(Bb + (long long)(16 + b_k) * N + (n0 + b_n4));
    }
    __syncthreads();

    for (int it = 0; it < NIT; ++it) {
        const int cur = it & 1;
        if (it + 1 < NIT) {
            const int nxt = cur ^ 1;
#pragma unroll
            for (int r = 0; r < AR; ++r) {
                int m = a_m + (r << 6);
                As[nxt][a_k4 + 0][m] = ra[r].x; As[nxt][a_k4 + 1][m] = ra[r].y;
                As[nxt][a_k4 + 2][m] = ra[r].z; As[nxt][a_k4 + 3][m] = ra[r].w;
            }
            *(float4*)(&Bs[nxt][b_k][b_n4]) = rb;
            if (it + 2 < NIT) {
                const int k0 = (it + 2) << 4;
#pragma unroll
                for (int r = 0; r < AR; ++r)
                    ra[r] = *(const float4*)(Ab + (long long)(m0 + a_m + (r << 6)) * lda + (k0 + a_k4));
                rb = *(const float4*)(Bb + (long long)(k0 + b_k) * N + (n0 + b_n4));
            }
        }
#pragma unroll
        for (int k = 0; k < 16; ++k) {
            float af[TM], bf[4];
#pragma unroll
            for (int i = 0; i < TM; i += 4)
                *(float4*)&af[i] = *(const float4*)&As[cur][k][ty * TM + i];
            *(float4*)&bf[0] = *(const float4*)&Bs[cur][k][tx << 2];
#pragma unroll
            for (int i = 0; i < TM; ++i)
#pragma unroll
                for (int j = 0; j < 4; ++j)
                    acc[i][j] = fmaf(af[i], bf[j], acc[i][j]);
        }
        __syncthreads();
    }

#pragma unroll
    for (int i = 0; i < TM; ++i) {
        int m = m0 + ty * TM + i;
        float rs = rscale ? rscale[(long long)bz2 * rsStride + m] : 1.f;
        float vals[4];
#pragma unroll
        for (int j = 0; j < 4; ++j) {
            float x = acc[i][j];
            if (bias) x += bias[n0 + (tx << 2) + j];
            x *= rs;
            if (doRelu) x = fmaxf(x, 0.f);
            vals[j] = x;
        }
        *(float4*)(Cb + (long long)m * N + n0 + (tx << 2)) = *(float4*)vals;
    }
}

// ---------------- Wcomb split-K reduce ---------------------------------------
__global__ __launch_bounds__(256) void wcomb_reduce(
    const float* __restrict__ Wp, float* __restrict__ Wc)
{
    int i = blockIdx.x * 256 + threadIdx.x;
    float s = 0.f;
#pragma unroll
    for (int z = 0; z < 16; ++z) s += Wp[z * (C_ * C_) + i];
    Wc[i] = s;
}

// ---------------- G split-K reduce: G = u ⊙ sum_z Gp[b*4+z] -----------------
__global__ __launch_bounds__(256) void greduce(
    const float* __restrict__ Gp, const float* __restrict__ u,
    float* __restrict__ G)
{
    int i = blockIdx.x * 256 + threadIdx.x;
    int b   = i >> 15;
    int rem = i & 32767;
    float s = 0.f;
#pragma unroll
    for (int z = 0; z < 4; ++z)
        s += Gp[(long long)((b << 2) + z) * (T_ * C_) + rem];
    G[i] = u[i >> 8] * s;
}

// ---------------- y split-K reduce: y = sum_z yp[z] + b2 --------------------
__global__ __launch_bounds__(256) void yreduce(
    const float* __restrict__ yp, const float* __restrict__ b2,
    float* __restrict__ y)
{
    int i = blockIdx.x * 256 + threadIdx.x;
    float s = 0.f;
#pragma unroll
    for (int z = 0; z < 3; ++z)
        s += yp[(long long)z * (B_ * T_ * C_) + i];
    y[i] = s + b2[i & (C_ - 1)];
}

// ---------------- tiled transpose -------------------------------------------
__global__ __launch_bounds__(256) void transpose_k(
    const float* __restrict__ in, float* __restrict__ out,
    int R, int Cc, long long sIn, long long sOut)
{
    __shared__ float t[32][33];
    const float* ib = in  + (long long)blockIdx.z * sIn;
    float*       ob = out + (long long)blockIdx.z * sOut;
    const int r0 = blockIdx.y << 5;
    const int c0 = blockIdx.x << 5;
    const int lx = threadIdx.x & 31;
    const int ly = threadIdx.x >> 5;
#pragma unroll
    for (int i = ly; i < 32; i += 8)
        t[i][lx] = ib[(long long)(r0 + i) * Cc + (c0 + lx)];
    __syncthreads();
#pragma unroll
    for (int i = ly; i < 32; i += 8)
        ob[(long long)(c0 + i) * R + (r0 + lx)] = t[lx][i];
}

// ---------------- bias prep --------------------------------------------------
__global__ __launch_bounds__(256) void prep_bias(
    const float* __restrict__ W_sK, const float* __restrict__ b_aQ,
    const float* __restrict__ b_sV,
    float* __restrict__ bc, float* __restrict__ bsV)
{
    __shared__ float red[256];
    const int c = blockIdx.x;
    const int tid = threadIdx.x;
    if (c == 0) bsV[tid] = b_sV[tid] * (1.f / (float)T_);
    const float* row = W_sK + (long long)c * HW_;
    float s = 0.f;
#pragma unroll
    for (int r = 0; r < 4; ++r) {
        int h = tid + (r << 8);
        s = fmaf(row[h], b_aQ[h], s);
    }
    red[tid] = s; __syncthreads();
    for (int st = 128; st; st >>= 1) { if (tid < st) red[tid] += red[tid + st]; __syncthreads(); }
    if (tid == 0) bc[c] = red[0];
}

// ---------------- masked softmax -> Kmat = exp(10*S - 10), in place ---------
__global__ __launch_bounds__(256) void softmax_kmat(
    float* __restrict__ ZK, const int* __restrict__ Ms)
{
    __shared__ float red[256];
    const int row = blockIdx.x;        // b*T + t
    const int b   = row >> 7;
    float* z = ZK + (long long)row * HW_;
    const int* mrow = Ms + b * HW_;
    const int tid = threadIdx.x;

    float zv[4]; int mv[4];
    float mx = -3.4e38f;
#pragma unroll
    for (int c = 0; c < 4; ++c) {
        int h = tid + (c << 8);
        zv[c] = z[h];
        mv[c] = mrow[h];
        if (mv[c]) mx = fmaxf(mx, zv[c]);
    }
    red[tid] = mx; __syncthreads();
    for (int s = 128; s; s >>= 1) { if (tid < s) red[tid] = fmaxf(red[tid], red[tid + s]); __syncthreads(); }
    mx = red[0]; __syncthreads();

    float ev[4], sum = 0.f;
#pragma unroll
    for (int c = 0; c < 4; ++c) {
        ev[c] = mv[c] ? expf(zv[c] - mx) : 0.f;
        sum += ev[c];
    }
    red[tid] = sum; __syncthreads();
    for (int s = 128; s; s >>= 1) { if (tid < s) red[tid] += red[tid + s]; __syncthreads(); }
    const float inv = 1.f / red[0];

#pragma unroll
    for (int c = 0; c < 4; ++c) {
        int h = tid + (c << 8);
        float S = ev[c] * inv;
        z[h] = expf(10.f * S - 10.f);     // exp(-(1-S)/0.1)
    }
}

// ---------------- cluster helpers --------------------------------------------
__device__ __forceinline__ uint32_t smem_u32(const void* p) {
    uint32_t a;
    asm("{ .reg .u64 t; cvta.to.shared.u64 t, %1; cvt.u32.u64 %0, t; }"
        : "=r"(a) : "l"(p));
    return a;
}
__device__ __forceinline__ void cluster_sync_() {
    asm volatile("barrier.cluster.arrive.aligned;" ::: "memory");
    asm volatile("barrier.cluster.wait.aligned;"  ::: "memory");
}
__device__ __forceinline__ float ld_peer_f32(uint32_t addr, uint32_t rank) {
    uint32_t r; float v;
    asm volatile("mapa.shared::cluster.u32 %0, %1, %2;" : "=r"(r) : "r"(addr), "r"(rank));
    asm volatile("ld.shared::cluster.f32 %0, [%1];"     : "=f"(v) : "r"(r));
    return v;
}

// ---------------- Sinkhorn: R15 skeleton + register-resident phase-2 rows ---
// Identical sync structure and phase-1 walk to the round-9/14/15 benched
// form. NEW: each thread caches its fixed 64-element phase-2 operand row
// (Kt[col*129 + (half<<6) + 0..63]) in registers once; phase 2 then issues
// only broadcast v-loads + FMA — the 64KB/iter phase-2 SMEM sweep vanishes
// from the crossbar. kreg[hh] == the exact value the benched loop loaded, in
// the same FMA order -> bit-identical results.
__global__ void __cluster_dims__(8, 1, 1) __launch_bounds__(256, 1)
sinkhorn(float* __restrict__ Km, const int* __restrict__ Ms,
         const int* __restrict__ nIterPtr,
         float* __restrict__ gu, float* __restrict__ gv)
{
    extern __shared__ float sm[];
    float* Kt   = sm;                   // 128 * 129
    float* u    = Kt + 128 * 129;       // 128
    float* v    = u  + 128;             // 128
    float* bv   = v  + 128;             // 128
    float* red  = bv + 128;             // 256
    float* pbuf = red + 256;            // 2 * 128

    const int rank = blockIdx.x;
    const int b    = blockIdx.y;
    const int h0   = rank << 7;
    const int tid  = threadIdx.x;

    const int* mrow = Ms + b * HW_;
    float msum = 0.f;
    for (int h = tid; h < HW_; h += 256) msum += (float)mrow[h];
    red[tid] = msum; __syncthreads();
    for (int s = 128; s; s >>= 1) { if (tid < s) red[tid] += red[tid + s]; __syncthreads(); }
    const float num_fg = red[0];
    __syncthreads();
    if (tid < 128) {
        bv[tid] = mrow[h0 + tid] ? 1.f / num_fg : 0.f;
        u[tid]  = 1.f / (float)T_;
    }

    float* Kb = Km + (long long)b * T_ * HW_ + h0;
    for (int idx = tid; idx < 128 * 128; idx += 256) {
        int t = idx >> 7, hl = idx & 127;
        Kt[t * 129 + hl] = Kb[(long long)t * HW_ + hl];
    }
    __syncthreads();

    const int niter = *nIterPtr;
    const int col  = tid & 127;
    const int half = tid >> 7;
    const uint32_t pbuf_addr = smem_u32(pbuf);

    // register-cache this thread's fixed phase-2 operand row (64 floats)
    float kreg[64];
    {
        const float* kp = Kt + col * 129 + (half << 6);
#pragma unroll
        for (int q = 0; q < 64; ++q) kreg[q] = kp[q];
    }

    for (int it = 0; it < niter; ++it) {
        const int p = it & 1;

        // phase 1: Ktu_h = sum_t K[t,h]*u[t]  (benched scalar walk, SMEM)
        float s1 = 0.f;
        {
            const float* kp = Kt + (half << 6) * 129 + col;
            const float* up = u + (half << 6);
#pragma unroll 8
            for (int t = 0; t < 64; ++t) s1 = fmaf(kp[t * 129], up[t], s1);
        }
        red[tid] = s1; __syncthreads();
        if (tid < 128) {
            float ktu = red[tid] + red[tid + 128];
            float bb = bv[tid];
            v[tid] = (bb > 0.f) ? bb / ktu : 0.f;
        }
        __syncthreads();

        // phase 2: partial Kv_t — operands from REGISTERS, v broadcast only
        float s2 = 0.f;
        {
            const float* vp = v + (half << 6);
#pragma unroll
            for (int hh = 0; hh < 64; ++hh) s2 = fmaf(kreg[hh], vp[hh], s2);
        }
        red[tid] = s2; __syncthreads();
        if (tid < 128) pbuf[(p << 7) + tid] = red[tid] + red[tid + 128];

        cluster_sync_();

        if (tid < 128) {
            float kv = 0.f;
#pragma unroll
            for (int r = 0; r < 8; ++r)
                kv += ld_peer_f32(pbuf_addr + (((p << 7) + tid) << 2), (uint32_t)r);
            u[tid] = (1.f / (float)T_) / kv;
        }
        __syncthreads();
    }

    if (tid < 128) {
        if (rank == 0) gu[b * T_ + tid] = u[tid];
        gv[b * HW_ + h0 + tid] = v[tid];
    }

    // epilogue: write Kmat ⊙ v back in place (u applied in greduce)
    for (int idx = tid; idx < 128 * 128; idx += 256) {
        int t = idx >> 7, hl = idx & 127;
        Kb[(long long)t * HW_ + hl] = Kt[t * 129 + hl] * v[hl];
    }

    cluster_sync_();
}

// ---------------- driver ------------------------------------------------------
extern "C" void kernel_launch(void* const* d_in, const int* in_sizes, int n_in,
                              void* d_out, int out_size)
{
    const float* F_a  = (const float*)d_in[0];
    const float* F_s  = (const float*)d_in[1];
    const int*   M_s  = (const int*)  d_in[2];
    const float* W_aQ = (const float*)d_in[3];
    const float* b_aQ = (const float*)d_in[4];
    const float* W_sK = (const float*)d_in[5];
    // d_in[6] = b_sK : per-(b,t)-row logit constant, cancels in softmax over k
    const float* W_sV = (const float*)d_in[7];
    const float* b_sV = (const float*)d_in[8];
    const float* W1   = (const float*)d_in[9];
    const float* b1   = (const float*)d_in[10];
    const float* W2   = (const float*)d_in[11];
    const float* b2   = (const float*)d_in[12];
    float* y = (float*)d_out;

    float *WkT, *FsT, *Wp, *Wc, *bc, *bsV, *Qw, *QK, *Gp, *G, *O, *H, *yp, *u, *v;
    int* itf;
    cudaGetSymbolAddress((void**)&WkT, g_WkT);
    cudaGetSymbolAddress((void**)&FsT, g_FsT);
    cudaGetSymbolAddress((void**)&Wp,  g_Wp);
    cudaGetSymbolAddress((void**)&Wc,  g_Wc);
    cudaGetSymbolAddress((void**)&bc,  g_bc);
    cudaGetSymbolAddress((void**)&bsV, g_bsV);
    cudaGetSymbolAddress((void**)&Qw,  g_Qw);
    cudaGetSymbolAddress((void**)&QK,  g_QK);
    cudaGetSymbolAddress((void**)&Gp,  g_Gp);
    cudaGetSymbolAddress((void**)&G,   g_G);
    cudaGetSymbolAddress((void**)&O,   g_O);
    cudaGetSymbolAddress((void**)&H,   g_H);
    cudaGetSymbolAddress((void**)&yp,  g_yp);
    cudaGetSymbolAddress((void**)&u,   g_u);
    cudaGetSymbolAddress((void**)&v,   g_v);
    cudaGetSymbolAddress((void**)&itf, g_iter_fallback);

    const int* iterp = (n_in > 13 && d_in[13]) ? (const int*)d_in[13]
                                               : (const int*)itf;

    const int SK_SMEM = (128 * 129 + 128 * 3 + 256 + 256) * 4;  // 69632 B
    cudaFuncSetAttribute(sinkhorn, cudaFuncAttributeMaxDynamicSharedMemorySize, SK_SMEM);

    // 0a) WkT = W_sK^T                 [256,1024] -> [1024,256]
    transpose_k<<<dim3(HW_ / 32, C_ / 32, 1), 256>>>(W_sK, WkT, C_, HW_, 0, 0);
    // 0b) FsT[b] = F_s[b]^T            [1024,256] -> [256,1024], batched
    transpose_k<<<dim3(C_ / 32, HW_ / 32, B_), 256>>>(
        F_s, FsT, HW_, C_, (long long)HW_ * C_, (long long)C_ * HW_);
    // 0c) bcomb + b_sV/T
    prep_bias<<<C_, 256>>>(W_sK, b_aQ, b_sV, bc, bsV);

    // 1) Wcomb split-K (16 chunks of 64, grid 256) + reduce
    sgemm<64><<<dim3(4, 4, 16), 256>>>(
        W_aQ, WkT, nullptr, nullptr, Wp,
        C_, C_, 64, HW_, 0, 0, (long long)C_ * C_, 0, 0, 16);
    wcomb_reduce<<<(C_ * C_) / 256, 256>>>(Wp, Wc);

    // 2) Qw = F_a @ Wcomb + bcomb      [2048,256] k=256 (NN, BM=64)
    sgemm<64><<<dim3(4, 32, 1), 256>>>(
        F_a, Wc, bc, nullptr, Qw, B_ * T_, C_, C_, C_, 0, 0, 0, 0, 0, 1);

    // 3) QK[b] = Qw[b] @ FsT[b]        batched [128,1024] k=256 (NN, BM=64)
    sgemm<64><<<dim3(16, 2, B_), 256>>>(
        Qw, FsT, nullptr, nullptr, QK, T_, HW_, C_, C_,
        (long long)T_ * C_, (long long)C_ * HW_, (long long)T_ * HW_, 0, 0, 1);

    // 4) masked softmax -> Kmat (in place)
    softmax_kmat<<<B_ * T_, 256>>>(QK, M_s);

    // 5) Sinkhorn -> u, v; epilogue writes Kmat⊙v in place
    sinkhorn<<<dim3(8, B_), 256, SK_SMEM>>>(QK, M_s, iterp, u, v);

    // 6) Gp split-K (z = b*4+c, grid 512); u applied in greduce
    sgemm<64><<<dim3(4, 2, B_ * 4), 256>>>(
        QK, F_s, nullptr, nullptr, Gp, T_, C_, 256, HW_,
        (long long)T_ * HW_, (long long)HW_ * C_, (long long)T_ * C_, 0, 0, 4);
    greduce<<<(B_ * T_ * C_) / 256, 256>>>(Gp, u, G);

    // 7) O = G @ W_sV + b_sV/T         [2048,256] k=256 (NN, BM=64)
    sgemm<64><<<dim3(4, 32, 1), 256>>>(
        G, W_sV, bsV, nullptr, O, B_ * T_, C_, C_, C_, 0, 0, 0, 0, 0, 1);

    // 8) H = relu(O @ W1 + b1)         [2048,768] k=256 (NN, BM=64)
    sgemm<64><<<dim3(12, 32, 1), 256>>>(
        O, W1, b1, nullptr, H, B_ * T_, 3 * C_, C_, C_, 0, 0, 0, 0, 1, 1);

    // 9) yp split-K 3 (grid 384) + reduce(+b2)
    sgemm<64><<<dim3(4, 32, 3), 256>>>(
        H, W2, nullptr, nullptr, yp, B_ * T_, C_, 256, 3 * C_,
        0, 0, (long long)B_ * T_ * C_, 0, 0, 3);
    yreduce<<<(B_ * T_ * C_) / 256, 256>>>(yp, b2, y);
}